// round 11
// baseline (speedup 1.0000x reference)
#include <cuda_runtime.h>
#include <cuda_bf16.h>
#include <cstdint>
#include <math.h>

#define SEQ   2048
#define DIM   512
#define KCB   8192
#define NROWS 16384
#define MARGIN  16.0f
#define RMARGIN 16.0f
#define MAXC  256

// ---------------- global scratch ----------------
__device__ __align__(16) __nv_bfloat16 g_xb[(size_t)NROWS * DIM];   // 16 MB
__device__ __align__(16) __nv_bfloat16 g_cb[(size_t)KCB * DIM];     // 8 MB
__device__ __align__(16) float g_c2[KCB];
__device__ __align__(16) float g_pe[(size_t)SEQ * DIM];             // 4 MB
__device__ int   g_cand[(size_t)NROWS * MAXC];
__device__ float g_cscore[(size_t)NROWS * MAXC];
__device__ int   g_ncand[NROWS];
__device__ float g_rowmin[NROWS];

// ---------------- helpers ----------------
__device__ __forceinline__ uint32_t smem_to_u32(const void* p) {
    uint32_t a;
    asm("{ .reg .u64 t; cvta.to.shared.u64 t, %1; cvt.u32.u64 %0, t; }" : "=r"(a) : "l"(p));
    return a;
}
__device__ __forceinline__ void ldsm4(uint32_t* r, uint32_t addr) {
    asm volatile("ldmatrix.sync.aligned.m8n8.x4.shared.b16 {%0,%1,%2,%3}, [%4];"
                 : "=r"(r[0]), "=r"(r[1]), "=r"(r[2]), "=r"(r[3]) : "r"(addr));
}
__device__ __forceinline__ void mma16816(float* c, const uint32_t* a, uint32_t b0, uint32_t b1) {
    asm volatile("mma.sync.aligned.m16n8k16.row.col.f32.bf16.bf16.f32 "
                 "{%0,%1,%2,%3}, {%4,%5,%6,%7}, {%8,%9}, {%0,%1,%2,%3};"
                 : "+f"(c[0]), "+f"(c[1]), "+f"(c[2]), "+f"(c[3])
                 : "r"(a[0]), "r"(a[1]), "r"(a[2]), "r"(a[3]), "r"(b0), "r"(b1));
}
__device__ __forceinline__ unsigned fmap(float f) {
    unsigned u = __float_as_uint(f);
    return (u >> 31) ? ~u : (u | 0x80000000u);
}
__device__ __forceinline__ float funmap(unsigned m) {
    return (m >> 31) ? __uint_as_float(m & 0x7fffffffu) : __uint_as_float(~m);
}

// ---------------- screening GEMM ----------------
// CTA: 128 rows x 8192 codes. 256 threads = 8 warps = 2 wm (m64) x 4 wn (n64).
// A resident in SMEM (128 x 1024B bf16, swizzled). B: 32 tiles of 256 codes,
// streamed in 8 chunks of k=64 (32 KB), double-buffered cp.async.
#define ATILE_B  131072
#define BCHUNK_B 32768            // 256 n * 64 k * 2 B, 128B rows
#define SMEM_DYN (ATILE_B + 2*BCHUNK_B + 1024)
#define NCHUNK   256              // 32 tiles * 8 chunks

__device__ __forceinline__ void issue_b(uint32_t dstbase, int chunk, int tid) {
    int tile = chunk >> 3, kc = chunk & 7;
    const uint4* base = (const uint4*)g_cb;
#pragma unroll
    for (int j = 0; j < 8; j++) {
        int idx = tid + j * 256;          // 0..2047 16B chunks
        int n = idx >> 3, c16 = idx & 7;  // code row 0..255, chunk 0..7 (128B rows)
        const uint4* sp = base + (size_t)(tile * 256 + n) * 64 + kc * 8 + c16;
        uint32_t d = dstbase + (uint32_t)(n * 128 + ((c16 * 16) ^ ((n & 7) << 4)));
        asm volatile("cp.async.cg.shared.global [%0], [%1], 16;" :: "r"(d), "l"(sp));
    }
}

__global__ void __launch_bounds__(256, 1) k_screen() {
    extern __shared__ char smem[];
    uint32_t sb = smem_to_u32(smem);
    uint32_t s0 = (sb + 1023) & ~1023u;
    const uint32_t A_B = s0;
    const uint32_t B_B0 = s0 + ATILE_B;
    __shared__ float c2s[256];
    __shared__ unsigned rowmin[128];

    const int tid = threadIdx.x, lane = tid & 31, warp = tid >> 5;
    const int wm = warp >> 2, wn = warp & 3;          // 2 x 4
    const int rowbase = blockIdx.x * 128;

    if (tid < 128) rowmin[tid] = 0xFFFFFFFFu;

    // Load A (swizzled: byte = r*1024 + ((2k) ^ ((r&7)<<4)))
    const uint4* ax = ((const uint4*)g_xb) + (size_t)rowbase * 64;
    for (int idx = tid; idx < 8192; idx += 256) {
        int r = idx >> 6, c16 = idx & 63;
        uint4 v = ax[idx];
        uint32_t d = A_B + (uint32_t)(r * 1024 + ((c16 * 16) ^ ((r & 7) << 4)));
        asm volatile("st.shared.v4.b32 [%0], {%1,%2,%3,%4};"
                     :: "r"(d), "r"(v.x), "r"(v.y), "r"(v.z), "r"(v.w));
    }

    const uint32_t xr  = (uint32_t)(lane & 7) << 4;
    const uint32_t aRow = A_B + (uint32_t)((wm * 64 + (lane & 7) + (lane & 8)) * 1024);
    const uint32_t akh = (uint32_t)((lane >> 4) & 1) * 16;
    const uint32_t bnoff = (uint32_t)((lane & 7) + ((lane & 16) >> 1));
    const uint32_t bkh = (uint32_t)((lane >> 3) & 1) * 16;
    const int g = lane >> 2;

    float acc[4][8][4];          // 4 m16-slices x 8 n8-slices x 4

    issue_b(B_B0, 0, tid);
    asm volatile("cp.async.commit_group;" ::: "memory");

    for (int ci = 0; ci < NCHUNK; ci++) {
        const int cur = ci & 1;
        asm volatile("cp.async.wait_group 0;" ::: "memory");
        __syncthreads();
        if (ci + 1 < NCHUNK) {
            issue_b(B_B0 + (uint32_t)((cur ^ 1) * BCHUNK_B), ci + 1, tid);
            asm volatile("cp.async.commit_group;" ::: "memory");
        }

        if ((ci & 7) == 0) {
            c2s[tid] = g_c2[(ci >> 3) * 256 + tid];
#pragma unroll
            for (int a = 0; a < 4; a++)
#pragma unroll
                for (int b = 0; b < 8; b++)
#pragma unroll
                    for (int c = 0; c < 4; c++) acc[a][b][c] = 0.f;
        }

        const uint32_t kbase = (uint32_t)((ci & 7) * 128);
        const uint32_t Bb = B_B0 + (uint32_t)(cur * BCHUNK_B) + (uint32_t)(wn * 64 + bnoff) * 128;

        // double-buffered fragments, explicit software pipeline over 4 ks
        uint32_t af[2][4][4], bf[2][4][4];
#define LOADF(st, ks) do { \
        uint32_t ka = (kbase + (uint32_t)(32 * (ks)) + akh) ^ xr; \
        uint32_t kb = ((uint32_t)(32 * (ks)) + bkh) ^ xr; \
        _Pragma("unroll") \
        for (int ms = 0; ms < 4; ms++) ldsm4(af[st][ms], aRow + (uint32_t)(ms * 16384) + ka); \
        _Pragma("unroll") \
        for (int p = 0; p < 4; p++) ldsm4(bf[st][p], Bb + (uint32_t)(p * 2048) + kb); \
    } while (0)

        LOADF(0, 0);
#pragma unroll
        for (int ks = 0; ks < 4; ks++) {
            const int c = ks & 1;
            if (ks < 3) LOADF(c ^ 1, ks + 1);
#pragma unroll
            for (int ms = 0; ms < 4; ms++)
#pragma unroll
                for (int p = 0; p < 4; p++) {
                    mma16816(acc[ms][2 * p],     af[c][ms], bf[c][p][0], bf[c][p][1]);
                    mma16816(acc[ms][2 * p + 1], af[c][ms], bf[c][p][2], bf[c][p][3]);
                }
        }
#undef LOADF

        if ((ci & 7) == 7) {
            const int tile = ci >> 3;
#pragma unroll
            for (int ms = 0; ms < 4; ms++)
#pragma unroll
                for (int h = 0; h < 2; h++) {
                    int r = wm * 64 + ms * 16 + 8 * h + g;
                    float sc[16];
                    float mn = 3.4e38f;
#pragma unroll
                    for (int ns = 0; ns < 8; ns++) {
                        int col = wn * 64 + ns * 8 + (lane & 3) * 2;
                        sc[2 * ns]     = fmaf(-2.f, acc[ms][ns][2 * h],     c2s[col]);
                        sc[2 * ns + 1] = fmaf(-2.f, acc[ms][ns][2 * h + 1], c2s[col + 1]);
                        mn = fminf(mn, fminf(sc[2 * ns], sc[2 * ns + 1]));
                    }
                    mn = fminf(mn, __shfl_xor_sync(0xffffffffu, mn, 1));
                    mn = fminf(mn, __shfl_xor_sync(0xffffffffu, mn, 2));
                    unsigned old = atomicMin(&rowmin[r], fmap(mn));
                    float thr = fminf(funmap(old), mn) + MARGIN;
                    int rg = rowbase + r;
#pragma unroll
                    for (int ns = 0; ns < 8; ns++) {
                        int col = wn * 64 + ns * 8 + (lane & 3) * 2;
                        if (sc[2 * ns] <= thr) {
                            int p = atomicAdd(&g_ncand[rg], 1);
                            if (p < MAXC) { g_cand[rg * MAXC + p] = tile * 256 + col; g_cscore[rg * MAXC + p] = sc[2 * ns]; }
                        }
                        if (sc[2 * ns + 1] <= thr) {
                            int p = atomicAdd(&g_ncand[rg], 1);
                            if (p < MAXC) { g_cand[rg * MAXC + p] = tile * 256 + col + 1; g_cscore[rg * MAXC + p] = sc[2 * ns + 1]; }
                        }
                    }
                }
        }
    }
    __syncthreads();
    if (tid < 128) g_rowmin[rowbase + tid] = funmap(rowmin[tid]);
}

// ---------------- pass 2: refilter + fp32 exact rescore + gather + PE ----------------
__global__ void __launch_bounds__(256) k_select(const float* __restrict__ x,
                                                const float* __restrict__ cb,
                                                float* __restrict__ out) {
    const int r = (blockIdx.x << 3) + (threadIdx.x >> 5);
    const int lane = threadIdx.x & 31;
    const int w = threadIdx.x >> 5;
    const int nc = g_ncand[r];
    __shared__ float xs[8][DIM];
    int bk;

    if (nc <= MAXC) {
        const float thr = g_rowmin[r] + RMARGIN;
        float bestv = 3.4e38f;
        int bkk = KCB;
        const float4* xr = ((const float4*)x) + (size_t)r * 128;
        float4 xv[4];
#pragma unroll
        for (int q = 0; q < 4; q++) xv[q] = xr[lane + q * 32];
        for (int ci = 0; ci < nc; ci++) {
            if (g_cscore[r * MAXC + ci] > thr) continue;
            int k = g_cand[r * MAXC + ci];
            const float4* cr = ((const float4*)cb) + (size_t)k * 128;
            float pd = 0.f;
#pragma unroll
            for (int q = 0; q < 4; q++) {
                float4 c = cr[lane + q * 32];
                pd = fmaf(xv[q].x, c.x, pd); pd = fmaf(xv[q].y, c.y, pd);
                pd = fmaf(xv[q].z, c.z, pd); pd = fmaf(xv[q].w, c.w, pd);
            }
#pragma unroll
            for (int o = 16; o; o >>= 1) pd += __shfl_down_sync(0xffffffffu, pd, o);
            if (lane == 0) {
                float d2 = fmaf(-2.0f, pd, g_c2[k]);
                if (d2 < bestv || (d2 == bestv && k < bkk)) { bestv = d2; bkk = k; }
            }
        }
        bk = __shfl_sync(0xffffffffu, bkk, 0);
    } else {
        for (int d = lane; d < DIM; d += 32) xs[w][d] = x[(size_t)r * DIM + d];
        __syncwarp();
        const float thrfb = g_rowmin[r] + RMARGIN;
        int kl[8]; int cnt = 0;
        for (int k0 = lane; k0 < KCB; k0 += 32) {
            const uint2* crow = (const uint2*)(g_cb + (size_t)k0 * DIM);
            float dot = 0.f;
#pragma unroll 4
            for (int q = 0; q < 128; q++) {
                uint2 u = crow[q];
                __nv_bfloat162 h0 = *(__nv_bfloat162*)&u.x, h1 = *(__nv_bfloat162*)&u.y;
                float2 f0 = __bfloat1622float2(h0), f1 = __bfloat1622float2(h1);
                dot += xs[w][4 * q] * f0.x + xs[w][4 * q + 1] * f0.y
                     + xs[w][4 * q + 2] * f1.x + xs[w][4 * q + 3] * f1.y;
            }
            float s = fmaf(-2.f, dot, g_c2[k0]);
            if (s <= thrfb && cnt < 8) kl[cnt++] = k0;
        }
        float bv = 3.4e38f; int bkk = KCB;
        for (int c = 0; c < cnt; c++) {
            int k = kl[c];
            const float* cr = cb + (size_t)k * DIM;
            float pd = 0.f;
            for (int d = 0; d < DIM; d++) pd = fmaf(xs[w][d], cr[d], pd);
            float d2 = fmaf(-2.0f, pd, g_c2[k]);
            if (d2 < bv || (d2 == bv && k < bkk)) { bv = d2; bkk = k; }
        }
        for (int o = 16; o; o >>= 1) {
            float ov = __shfl_down_sync(0xffffffffu, bv, o);
            int ok = __shfl_down_sync(0xffffffffu, bkk, o);
            if (ov < bv || (ov == bv && ok < bkk)) { bv = ov; bkk = ok; }
        }
        bk = __shfl_sync(0xffffffffu, bkk, 0);
    }

    const int s = r & (SEQ - 1);
    const float4* cr = ((const float4*)cb) + (size_t)bk * 128;
    const float4* pr = ((const float4*)g_pe) + (size_t)s * 128;
    float4* o4 = ((float4*)out) + (size_t)r * 128;
#pragma unroll
    for (int q = 0; q < 4; q++) {
        float4 c = cr[lane + q * 32], p = pr[lane + q * 32];
        o4[lane + q * 32] = make_float4(c.x + p.x, c.y + p.y, c.z + p.z, c.w + p.w);
    }
}

// ---------------- prep kernels ----------------
__global__ void k_prep_x(const float4* __restrict__ x) {
    int i = blockIdx.x * blockDim.x + threadIdx.x;
    if (i < NROWS * DIM / 4) {
        float4 v = x[i];
        __nv_bfloat162 a = __floats2bfloat162_rn(v.x, v.y);
        __nv_bfloat162 b = __floats2bfloat162_rn(v.z, v.w);
        reinterpret_cast<uint2*>(g_xb)[i] =
            make_uint2(*reinterpret_cast<uint32_t*>(&a), *reinterpret_cast<uint32_t*>(&b));
    }
    if (i < NROWS) g_ncand[i] = 0;
}

__global__ void k_prep_cb(const float* __restrict__ cb) {
    int row = blockIdx.x, tid = threadIdx.x;
    float p = 0.0f;
    for (int d = tid; d < DIM; d += 128) {
        float v = cb[(size_t)row * DIM + d];
        g_cb[(size_t)row * DIM + d] = __float2bfloat16(v);
        p = fmaf(v, v, p);
    }
#pragma unroll
    for (int off = 16; off; off >>= 1) p += __shfl_down_sync(0xffffffffu, p, off);
    __shared__ float r4[4];
    if ((tid & 31) == 0) r4[tid >> 5] = p;
    __syncthreads();
    if (tid == 0) g_c2[row] = r4[0] + r4[1] + r4[2] + r4[3];
}

__global__ void k_prep_pe() {
    int s = blockIdx.x;
    int i = threadIdx.x;
    const float c = (float)(9.210340371976184 / 512.0);
    float dvf = expf(-(float)(2 * i) * c);
    float angf = (float)s * dvf;
    float n = rintf(angf * 0.15915494309189535f);
    float rf = (float)((double)angf - (double)n * 6.283185307179586477);
    g_pe[(size_t)s * DIM + 2 * i]     = sinf(rf);
    g_pe[(size_t)s * DIM + 2 * i + 1] = cosf(rf);
}

// ---------------- launch ----------------
extern "C" void kernel_launch(void* const* d_in, const int* in_sizes, int n_in,
                              void* d_out, int out_size) {
    const float* x  = (const float*)d_in[0];
    const float* cb = (const float*)d_in[1];
    float* out = (float*)d_out;

    cudaFuncSetAttribute(k_screen, cudaFuncAttributeMaxDynamicSharedMemorySize, SMEM_DYN);

    k_prep_x<<<(NROWS * DIM / 4 + 255) / 256, 256>>>((const float4*)x);
    k_prep_cb<<<KCB, 128>>>(cb);
    k_prep_pe<<<SEQ, 256>>>();
    k_screen<<<128, 256, SMEM_DYN>>>();
    k_select<<<NROWS / 8, 256>>>(x, cb, out);
}

// round 12
// speedup vs baseline: 1.0967x; 1.0967x over previous
#include <cuda_runtime.h>
#include <cuda_bf16.h>
#include <cstdint>
#include <math.h>

#define SEQ   2048
#define DIM   512
#define KCB   8192
#define NROWS 16384
#define MARGIN  16.0f
#define RMARGIN 16.0f
#define MAXC  256

// ---------------- global scratch ----------------
__device__ __align__(16) __nv_bfloat16 g_xb[(size_t)NROWS * DIM];   // 16 MB
__device__ __align__(16) __nv_bfloat16 g_cb[(size_t)KCB * DIM];     // 8 MB
__device__ __align__(16) float g_c2[KCB];
__device__ __align__(16) float g_pe[(size_t)SEQ * DIM];             // 4 MB
__device__ int   g_cand[(size_t)NROWS * MAXC];
__device__ float g_cscore[(size_t)NROWS * MAXC];
__device__ int   g_ncand[NROWS];
__device__ float g_rowmin[NROWS];

// ---------------- helpers ----------------
__device__ __forceinline__ uint32_t smem_to_u32(const void* p) {
    uint32_t a;
    asm("{ .reg .u64 t; cvta.to.shared.u64 t, %1; cvt.u32.u64 %0, t; }" : "=r"(a) : "l"(p));
    return a;
}
__device__ __forceinline__ void ldsm4(uint32_t* r, uint32_t addr) {
    asm volatile("ldmatrix.sync.aligned.m8n8.x4.shared.b16 {%0,%1,%2,%3}, [%4];"
                 : "=r"(r[0]), "=r"(r[1]), "=r"(r[2]), "=r"(r[3]) : "r"(addr));
}
__device__ __forceinline__ void mma16816(float* c, const uint32_t* a, uint32_t b0, uint32_t b1) {
    asm volatile("mma.sync.aligned.m16n8k16.row.col.f32.bf16.bf16.f32 "
                 "{%0,%1,%2,%3}, {%4,%5,%6,%7}, {%8,%9}, {%0,%1,%2,%3};"
                 : "+f"(c[0]), "+f"(c[1]), "+f"(c[2]), "+f"(c[3])
                 : "r"(a[0]), "r"(a[1]), "r"(a[2]), "r"(a[3]), "r"(b0), "r"(b1));
}
__device__ __forceinline__ unsigned fmap(float f) {
    unsigned u = __float_as_uint(f);
    return (u >> 31) ? ~u : (u | 0x80000000u);
}
__device__ __forceinline__ float funmap(unsigned m) {
    return (m >> 31) ? __uint_as_float(m & 0x7fffffffu) : __uint_as_float(~m);
}

// ---------------- screening GEMM ----------------
// CTA: 64 rows x 8192 codes, 256 threads = 8 warps = 2 wm (m32) x 4 wn (n32).
// 2 CTAs per SM (decoupled barriers). A resident 64 KB. B: 64 tiles of 128
// codes, k64 chunks (16 KB), double-buffered cp.async. Grid 256.
#define ATILE_B  65536            // 64 rows * 1024 B
#define BCHUNK_B 16384            // 128 n * 64 k * 2 B, 128B rows
#define SMEM_DYN (ATILE_B + 2*BCHUNK_B + 1024)
#define NCHUNK   512              // 64 tiles * 8 chunks

__device__ __forceinline__ void issue_b(uint32_t dstbase, int chunk, int tid) {
    int tile = chunk >> 3, kc = chunk & 7;
    const uint4* base = (const uint4*)g_cb;
#pragma unroll
    for (int j = 0; j < 4; j++) {
        int idx = tid + j * 256;          // 0..1023 16B chunks
        int n = idx >> 3, c16 = idx & 7;  // code row 0..127, chunk 0..7 (128B rows)
        const uint4* sp = base + (size_t)(tile * 128 + n) * 64 + kc * 8 + c16;
        uint32_t d = dstbase + (uint32_t)(n * 128 + ((c16 * 16) ^ ((n & 7) << 4)));
        asm volatile("cp.async.cg.shared.global [%0], [%1], 16;" :: "r"(d), "l"(sp));
    }
}

__global__ void __launch_bounds__(256, 2) k_screen() {
    extern __shared__ char smem[];
    uint32_t sb = smem_to_u32(smem);
    uint32_t s0 = (sb + 1023) & ~1023u;
    const uint32_t A_B = s0;
    const uint32_t B_B0 = s0 + ATILE_B;
    __shared__ float c2s[128];
    __shared__ unsigned rowmin[64];

    const int tid = threadIdx.x, lane = tid & 31, warp = tid >> 5;
    const int wm = warp >> 2, wn = warp & 3;          // 2 x 4
    const int rowbase = blockIdx.x * 64;

    if (tid < 64) rowmin[tid] = 0xFFFFFFFFu;

    // Load A (64 rows, swizzled: byte = r*1024 + ((2k) ^ ((r&7)<<4)))
    const uint4* ax = ((const uint4*)g_xb) + (size_t)rowbase * 64;
    for (int idx = tid; idx < 4096; idx += 256) {
        int r = idx >> 6, c16 = idx & 63;
        uint4 v = ax[idx];
        uint32_t d = A_B + (uint32_t)(r * 1024 + ((c16 * 16) ^ ((r & 7) << 4)));
        asm volatile("st.shared.v4.b32 [%0], {%1,%2,%3,%4};"
                     :: "r"(d), "r"(v.x), "r"(v.y), "r"(v.z), "r"(v.w));
    }

    const uint32_t xr  = (uint32_t)(lane & 7) << 4;
    const uint32_t aRow = A_B + (uint32_t)((wm * 32 + (lane & 7) + (lane & 8)) * 1024);
    const uint32_t akh = (uint32_t)((lane >> 4) & 1) * 16;
    const uint32_t bnoff = (uint32_t)((lane & 7) + ((lane & 16) >> 1));
    const uint32_t bkh = (uint32_t)((lane >> 3) & 1) * 16;
    const int g = lane >> 2;

    float acc[2][4][4];           // 2 m16-slices x 4 n8-slices x 4

    issue_b(B_B0, 0, tid);
    asm volatile("cp.async.commit_group;" ::: "memory");

    for (int ci = 0; ci < NCHUNK; ci++) {
        const int cur = ci & 1;
        asm volatile("cp.async.wait_group 0;" ::: "memory");
        __syncthreads();
        if (ci + 1 < NCHUNK) {
            issue_b(B_B0 + (uint32_t)((cur ^ 1) * BCHUNK_B), ci + 1, tid);
            asm volatile("cp.async.commit_group;" ::: "memory");
        }

        if ((ci & 7) == 0) {
            if (tid < 128) c2s[tid] = g_c2[(ci >> 3) * 128 + tid];
#pragma unroll
            for (int a = 0; a < 2; a++)
#pragma unroll
                for (int b = 0; b < 4; b++)
#pragma unroll
                    for (int c = 0; c < 4; c++) acc[a][b][c] = 0.f;
        }

        const uint32_t kbase = (uint32_t)((ci & 7) * 128);   // A-row byte offset (k64 chunk)
        const uint32_t Bb = B_B0 + (uint32_t)(cur * BCHUNK_B) + (uint32_t)(wn * 32 + bnoff) * 128;

        // double-buffered fragments, software pipeline over 4 ks
        uint32_t af[2][2][4], bf[2][2][4];
#define LOADF(st, ks) do { \
        uint32_t ka = (kbase + (uint32_t)(32 * (ks)) + akh) ^ xr; \
        uint32_t kb = ((uint32_t)(32 * (ks)) + bkh) ^ xr; \
        _Pragma("unroll") \
        for (int ms = 0; ms < 2; ms++) ldsm4(af[st][ms], aRow + (uint32_t)(ms * 16384) + ka); \
        _Pragma("unroll") \
        for (int p = 0; p < 2; p++) ldsm4(bf[st][p], Bb + (uint32_t)(p * 2048) + kb); \
    } while (0)

        LOADF(0, 0);
#pragma unroll
        for (int ks = 0; ks < 4; ks++) {
            const int c = ks & 1;
            if (ks < 3) LOADF(c ^ 1, ks + 1);
#pragma unroll
            for (int ms = 0; ms < 2; ms++)
#pragma unroll
                for (int p = 0; p < 2; p++) {
                    mma16816(acc[ms][2 * p],     af[c][ms], bf[c][p][0], bf[c][p][1]);
                    mma16816(acc[ms][2 * p + 1], af[c][ms], bf[c][p][2], bf[c][p][3]);
                }
        }
#undef LOADF

        if ((ci & 7) == 7) {
            const int tile = ci >> 3;
#pragma unroll
            for (int ms = 0; ms < 2; ms++)
#pragma unroll
                for (int h = 0; h < 2; h++) {
                    int r = wm * 32 + ms * 16 + 8 * h + g;
                    float sc[8];
                    float mn = 3.4e38f;
#pragma unroll
                    for (int ns = 0; ns < 4; ns++) {
                        int col = wn * 32 + ns * 8 + (lane & 3) * 2;
                        sc[2 * ns]     = fmaf(-2.f, acc[ms][ns][2 * h],     c2s[col]);
                        sc[2 * ns + 1] = fmaf(-2.f, acc[ms][ns][2 * h + 1], c2s[col + 1]);
                        mn = fminf(mn, fminf(sc[2 * ns], sc[2 * ns + 1]));
                    }
                    mn = fminf(mn, __shfl_xor_sync(0xffffffffu, mn, 1));
                    mn = fminf(mn, __shfl_xor_sync(0xffffffffu, mn, 2));
                    unsigned old = atomicMin(&rowmin[r], fmap(mn));
                    float thr = fminf(funmap(old), mn) + MARGIN;
                    int rg = rowbase + r;
#pragma unroll
                    for (int ns = 0; ns < 4; ns++) {
                        int col = wn * 32 + ns * 8 + (lane & 3) * 2;
                        if (sc[2 * ns] <= thr) {
                            int p = atomicAdd(&g_ncand[rg], 1);
                            if (p < MAXC) { g_cand[rg * MAXC + p] = tile * 128 + col; g_cscore[rg * MAXC + p] = sc[2 * ns]; }
                        }
                        if (sc[2 * ns + 1] <= thr) {
                            int p = atomicAdd(&g_ncand[rg], 1);
                            if (p < MAXC) { g_cand[rg * MAXC + p] = tile * 128 + col + 1; g_cscore[rg * MAXC + p] = sc[2 * ns + 1]; }
                        }
                    }
                }
        }
    }
    __syncthreads();
    if (tid < 64) g_rowmin[rowbase + tid] = funmap(rowmin[tid]);
}

// ---------------- pass 2: refilter + fp32 exact rescore + gather + PE ----------------
__global__ void __launch_bounds__(256) k_select(const float* __restrict__ x,
                                                const float* __restrict__ cb,
                                                float* __restrict__ out) {
    const int r = (blockIdx.x << 3) + (threadIdx.x >> 5);
    const int lane = threadIdx.x & 31;
    const int w = threadIdx.x >> 5;
    const int nc = g_ncand[r];
    __shared__ float xs[8][DIM];
    int bk;

    if (nc <= MAXC) {
        const float thr = g_rowmin[r] + RMARGIN;
        float bestv = 3.4e38f;
        int bkk = KCB;
        const float4* xr = ((const float4*)x) + (size_t)r * 128;
        float4 xv[4];
#pragma unroll
        for (int q = 0; q < 4; q++) xv[q] = xr[lane + q * 32];
        for (int ci = 0; ci < nc; ci++) {
            if (g_cscore[r * MAXC + ci] > thr) continue;
            int k = g_cand[r * MAXC + ci];
            const float4* cr = ((const float4*)cb) + (size_t)k * 128;
            float pd = 0.f;
#pragma unroll
            for (int q = 0; q < 4; q++) {
                float4 c = cr[lane + q * 32];
                pd = fmaf(xv[q].x, c.x, pd); pd = fmaf(xv[q].y, c.y, pd);
                pd = fmaf(xv[q].z, c.z, pd); pd = fmaf(xv[q].w, c.w, pd);
            }
#pragma unroll
            for (int o = 16; o; o >>= 1) pd += __shfl_down_sync(0xffffffffu, pd, o);
            if (lane == 0) {
                float d2 = fmaf(-2.0f, pd, g_c2[k]);
                if (d2 < bestv || (d2 == bestv && k < bkk)) { bestv = d2; bkk = k; }
            }
        }
        bk = __shfl_sync(0xffffffffu, bkk, 0);
    } else {
        for (int d = lane; d < DIM; d += 32) xs[w][d] = x[(size_t)r * DIM + d];
        __syncwarp();
        const float thrfb = g_rowmin[r] + RMARGIN;
        int kl[8]; int cnt = 0;
        for (int k0 = lane; k0 < KCB; k0 += 32) {
            const uint2* crow = (const uint2*)(g_cb + (size_t)k0 * DIM);
            float dot = 0.f;
#pragma unroll 4
            for (int q = 0; q < 128; q++) {
                uint2 u = crow[q];
                __nv_bfloat162 h0 = *(__nv_bfloat162*)&u.x, h1 = *(__nv_bfloat162*)&u.y;
                float2 f0 = __bfloat1622float2(h0), f1 = __bfloat1622float2(h1);
                dot += xs[w][4 * q] * f0.x + xs[w][4 * q + 1] * f0.y
                     + xs[w][4 * q + 2] * f1.x + xs[w][4 * q + 3] * f1.y;
            }
            float s = fmaf(-2.f, dot, g_c2[k0]);
            if (s <= thrfb && cnt < 8) kl[cnt++] = k0;
        }
        float bv = 3.4e38f; int bkk = KCB;
        for (int c = 0; c < cnt; c++) {
            int k = kl[c];
            const float* cr = cb + (size_t)k * DIM;
            float pd = 0.f;
            for (int d = 0; d < DIM; d++) pd = fmaf(xs[w][d], cr[d], pd);
            float d2 = fmaf(-2.0f, pd, g_c2[k]);
            if (d2 < bv || (d2 == bv && k < bkk)) { bv = d2; bkk = k; }
        }
        for (int o = 16; o; o >>= 1) {
            float ov = __shfl_down_sync(0xffffffffu, bv, o);
            int ok = __shfl_down_sync(0xffffffffu, bkk, o);
            if (ov < bv || (ov == bv && ok < bkk)) { bv = ov; bkk = ok; }
        }
        bk = __shfl_sync(0xffffffffu, bkk, 0);
    }

    const int s = r & (SEQ - 1);
    const float4* cr = ((const float4*)cb) + (size_t)bk * 128;
    const float4* pr = ((const float4*)g_pe) + (size_t)s * 128;
    float4* o4 = ((float4*)out) + (size_t)r * 128;
#pragma unroll
    for (int q = 0; q < 4; q++) {
        float4 c = cr[lane + q * 32], p = pr[lane + q * 32];
        o4[lane + q * 32] = make_float4(c.x + p.x, c.y + p.y, c.z + p.z, c.w + p.w);
    }
}

// ---------------- prep kernels ----------------
__global__ void k_prep_x(const float4* __restrict__ x) {
    int i = blockIdx.x * blockDim.x + threadIdx.x;
    if (i < NROWS * DIM / 4) {
        float4 v = x[i];
        __nv_bfloat162 a = __floats2bfloat162_rn(v.x, v.y);
        __nv_bfloat162 b = __floats2bfloat162_rn(v.z, v.w);
        reinterpret_cast<uint2*>(g_xb)[i] =
            make_uint2(*reinterpret_cast<uint32_t*>(&a), *reinterpret_cast<uint32_t*>(&b));
    }
    if (i < NROWS) g_ncand[i] = 0;
}

__global__ void k_prep_cb(const float* __restrict__ cb) {
    int row = blockIdx.x, tid = threadIdx.x;
    float p = 0.0f;
    for (int d = tid; d < DIM; d += 128) {
        float v = cb[(size_t)row * DIM + d];
        g_cb[(size_t)row * DIM + d] = __float2bfloat16(v);
        p = fmaf(v, v, p);
    }
#pragma unroll
    for (int off = 16; off; off >>= 1) p += __shfl_down_sync(0xffffffffu, p, off);
    __shared__ float r4[4];
    if ((tid & 31) == 0) r4[tid >> 5] = p;
    __syncthreads();
    if (tid == 0) g_c2[row] = r4[0] + r4[1] + r4[2] + r4[3];
}

__global__ void k_prep_pe() {
    int s = blockIdx.x;
    int i = threadIdx.x;
    const float c = (float)(9.210340371976184 / 512.0);
    float dvf = expf(-(float)(2 * i) * c);
    float angf = (float)s * dvf;
    float n = rintf(angf * 0.15915494309189535f);
    float rf = (float)((double)angf - (double)n * 6.283185307179586477);
    g_pe[(size_t)s * DIM + 2 * i]     = sinf(rf);
    g_pe[(size_t)s * DIM + 2 * i + 1] = cosf(rf);
}

// ---------------- launch ----------------
extern "C" void kernel_launch(void* const* d_in, const int* in_sizes, int n_in,
                              void* d_out, int out_size) {
    const float* x  = (const float*)d_in[0];
    const float* cb = (const float*)d_in[1];
    float* out = (float*)d_out;

    cudaFuncSetAttribute(k_screen, cudaFuncAttributeMaxDynamicSharedMemorySize, SMEM_DYN);

    k_prep_x<<<(NROWS * DIM / 4 + 255) / 256, 256>>>((const float4*)x);
    k_prep_cb<<<KCB, 128>>>(cb);
    k_prep_pe<<<SEQ, 256>>>();
    k_screen<<<NROWS / 64, 256, SMEM_DYN>>>();
    k_select<<<NROWS / 8, 256>>>(x, cb, out);
}

// round 13
// speedup vs baseline: 1.1320x; 1.0322x over previous
#include <cuda_runtime.h>
#include <cuda_fp16.h>
#include <cstdint>
#include <math.h>

#define SEQ   2048
#define DIM   512
#define KCB   8192
#define NROWS 16384
#define MARGIN  16.0f
#define RMARGIN 16.0f
#define MAXC  256

// ---------------- global scratch ----------------
__device__ __align__(16) __half g_xh[(size_t)NROWS * DIM];          // 16 MB
__device__ __align__(16) __half g_ch[(size_t)KCB * DIM];            // 8 MB
__device__ __align__(16) float g_c2[KCB];
__device__ __align__(16) float g_pe[(size_t)SEQ * DIM];             // 4 MB
__device__ int   g_cand[(size_t)NROWS * MAXC];
__device__ float g_cscore[(size_t)NROWS * MAXC];
__device__ int   g_ncand[NROWS];
__device__ float g_rowmin[NROWS];

// ---------------- helpers ----------------
__device__ __forceinline__ uint32_t smem_to_u32(const void* p) {
    uint32_t a;
    asm("{ .reg .u64 t; cvta.to.shared.u64 t, %1; cvt.u32.u64 %0, t; }" : "=r"(a) : "l"(p));
    return a;
}
__device__ __forceinline__ void ldsm4(uint32_t* r, uint32_t addr) {
    asm volatile("ldmatrix.sync.aligned.m8n8.x4.shared.b16 {%0,%1,%2,%3}, [%4];"
                 : "=r"(r[0]), "=r"(r[1]), "=r"(r[2]), "=r"(r[3]) : "r"(addr));
}
// f16 inputs, f16 accumulate: C/D fragment = 2 regs (4 halves)
__device__ __forceinline__ void mma16816h(uint32_t* c, const uint32_t* a, uint32_t b0, uint32_t b1) {
    asm volatile("mma.sync.aligned.m16n8k16.row.col.f16.f16.f16.f16 "
                 "{%0,%1}, {%2,%3,%4,%5}, {%6,%7}, {%0,%1};"
                 : "+r"(c[0]), "+r"(c[1])
                 : "r"(a[0]), "r"(a[1]), "r"(a[2]), "r"(a[3]), "r"(b0), "r"(b1));
}
__device__ __forceinline__ unsigned fmap(float f) {
    unsigned u = __float_as_uint(f);
    return (u >> 31) ? ~u : (u | 0x80000000u);
}
__device__ __forceinline__ float funmap(unsigned m) {
    return (m >> 31) ? __uint_as_float(m & 0x7fffffffu) : __uint_as_float(~m);
}

// ---------------- screening GEMM (round-10 config, fp16 accum) ----------------
// CTA: 128 rows x 8192 codes. 512 threads = 16 warps = 4 wm (m32) x 4 wn (n64).
// A resident in SMEM (128 x 1024B, swizzled). B: 32 tiles of 256 codes,
// k64 chunks (32 KB), double-buffered cp.async.
#define ATILE_B  131072
#define BCHUNK_B 32768            // 256 n * 64 k * 2 B, 128B rows
#define SMEM_DYN (ATILE_B + 2*BCHUNK_B + 1024)
#define NCHUNK   256              // 32 tiles * 8 chunks

__device__ __forceinline__ void issue_b(uint32_t dstbase, int chunk, int tid) {
    int tile = chunk >> 3, kc = chunk & 7;
    const uint4* base = (const uint4*)g_ch;
#pragma unroll
    for (int j = 0; j < 4; j++) {
        int idx = tid + j * 512;          // 0..2047 16B chunks
        int n = idx >> 3, c16 = idx & 7;  // code row 0..255, chunk 0..7 (128B rows)
        const uint4* sp = base + (size_t)(tile * 256 + n) * 64 + kc * 8 + c16;
        uint32_t d = dstbase + (uint32_t)(n * 128 + ((c16 * 16) ^ ((n & 7) << 4)));
        asm volatile("cp.async.cg.shared.global [%0], [%1], 16;" :: "r"(d), "l"(sp));
    }
}

__global__ void __launch_bounds__(512, 1) k_screen() {
    extern __shared__ char smem[];
    uint32_t sb = smem_to_u32(smem);
    uint32_t s0 = (sb + 1023) & ~1023u;
    const uint32_t A_B = s0;
    const uint32_t B_B0 = s0 + ATILE_B;
    __shared__ float c2s[256];
    __shared__ unsigned rowmin[128];

    const int tid = threadIdx.x, lane = tid & 31, warp = tid >> 5;
    const int wm = warp >> 2, wn = warp & 3;          // 4 x 4
    const int rowbase = blockIdx.x * 128;

    if (tid < 128) rowmin[tid] = 0xFFFFFFFFu;

    const uint4* ax = ((const uint4*)g_xh) + (size_t)rowbase * 64;
    for (int idx = tid; idx < 8192; idx += 512) {
        int r = idx >> 6, c16 = idx & 63;
        uint4 v = ax[idx];
        uint32_t d = A_B + (uint32_t)(r * 1024 + ((c16 * 16) ^ ((r & 7) << 4)));
        asm volatile("st.shared.v4.b32 [%0], {%1,%2,%3,%4};"
                     :: "r"(d), "r"(v.x), "r"(v.y), "r"(v.z), "r"(v.w));
    }

    const uint32_t xr  = (uint32_t)(lane & 7) << 4;
    const uint32_t aRow = A_B + (uint32_t)((wm * 32 + (lane & 7) + (lane & 8)) * 1024);
    const uint32_t akh = (uint32_t)((lane >> 4) & 1) * 16;
    const uint32_t bnoff = (uint32_t)((lane & 7) + ((lane & 16) >> 1));
    const uint32_t bkh = (uint32_t)((lane >> 3) & 1) * 16;
    const int g = lane >> 2;

    uint32_t acc[2][8][2];        // f16x2 accumulators: [ms][ns][h-reg]

    issue_b(B_B0, 0, tid);
    asm volatile("cp.async.commit_group;" ::: "memory");

    for (int ci = 0; ci < NCHUNK; ci++) {
        const int cur = ci & 1;
        asm volatile("cp.async.wait_group 0;" ::: "memory");
        __syncthreads();
        if (ci + 1 < NCHUNK) {
            issue_b(B_B0 + (uint32_t)((cur ^ 1) * BCHUNK_B), ci + 1, tid);
            asm volatile("cp.async.commit_group;" ::: "memory");
        }

        if ((ci & 7) == 0) {
            if (tid < 256) c2s[tid] = g_c2[(ci >> 3) * 256 + tid];
#pragma unroll
            for (int a = 0; a < 2; a++)
#pragma unroll
                for (int b = 0; b < 8; b++) { acc[a][b][0] = 0u; acc[a][b][1] = 0u; }
        }

        const uint32_t kbase = (uint32_t)((ci & 7) * 128);
        const uint32_t Bb = B_B0 + (uint32_t)(cur * BCHUNK_B) + (uint32_t)(wn * 64 + bnoff) * 128;
#pragma unroll
        for (int ks = 0; ks < 4; ks++) {
            uint32_t ka = (kbase + (uint32_t)(32 * ks) + akh) ^ xr;
            uint32_t kb = ((uint32_t)(32 * ks) + bkh) ^ xr;
            uint32_t a0[4], a1[4];
            ldsm4(a0, aRow + ka);
            ldsm4(a1, aRow + 16 * 1024 + ka);
            uint32_t bv[4][4];
#pragma unroll
            for (int p = 0; p < 4; p++) ldsm4(bv[p], Bb + (uint32_t)(p * 16 * 128) + kb);
#pragma unroll
            for (int p = 0; p < 4; p++) {
                mma16816h(acc[0][2 * p],     a0, bv[p][0], bv[p][1]);
                mma16816h(acc[0][2 * p + 1], a0, bv[p][2], bv[p][3]);
                mma16816h(acc[1][2 * p],     a1, bv[p][0], bv[p][1]);
                mma16816h(acc[1][2 * p + 1], a1, bv[p][2], bv[p][3]);
            }
        }

        if ((ci & 7) == 7) {
            const int tile = ci >> 3;
#pragma unroll
            for (int ms = 0; ms < 2; ms++)
#pragma unroll
                for (int h = 0; h < 2; h++) {
                    int r = wm * 32 + ms * 16 + 8 * h + g;
                    float sc[16];
                    float mn = 3.4e38f;
#pragma unroll
                    for (int ns = 0; ns < 8; ns++) {
                        int col = wn * 64 + ns * 8 + (lane & 3) * 2;
                        float2 dd = __half22float2(*(__half2*)&acc[ms][ns][h]);
                        sc[2 * ns]     = fmaf(-2.f, dd.x, c2s[col]);
                        sc[2 * ns + 1] = fmaf(-2.f, dd.y, c2s[col + 1]);
                        mn = fminf(mn, fminf(sc[2 * ns], sc[2 * ns + 1]));
                    }
                    mn = fminf(mn, __shfl_xor_sync(0xffffffffu, mn, 1));
                    mn = fminf(mn, __shfl_xor_sync(0xffffffffu, mn, 2));
                    unsigned old = atomicMin(&rowmin[r], fmap(mn));
                    float thr = fminf(funmap(old), mn) + MARGIN;
                    int rg = rowbase + r;
#pragma unroll
                    for (int ns = 0; ns < 8; ns++) {
                        int col = wn * 64 + ns * 8 + (lane & 3) * 2;
                        if (sc[2 * ns] <= thr) {
                            int p = atomicAdd(&g_ncand[rg], 1);
                            if (p < MAXC) { g_cand[rg * MAXC + p] = tile * 256 + col; g_cscore[rg * MAXC + p] = sc[2 * ns]; }
                        }
                        if (sc[2 * ns + 1] <= thr) {
                            int p = atomicAdd(&g_ncand[rg], 1);
                            if (p < MAXC) { g_cand[rg * MAXC + p] = tile * 256 + col + 1; g_cscore[rg * MAXC + p] = sc[2 * ns + 1]; }
                        }
                    }
                }
        }
    }
    __syncthreads();
    if (tid < 128) g_rowmin[rowbase + tid] = funmap(rowmin[tid]);
}

// ---------------- pass 2: refilter + fp32 exact rescore + gather + PE ----------------
__global__ void __launch_bounds__(256) k_select(const float* __restrict__ x,
                                                const float* __restrict__ cb,
                                                float* __restrict__ out) {
    const int r = (blockIdx.x << 3) + (threadIdx.x >> 5);
    const int lane = threadIdx.x & 31;
    const int w = threadIdx.x >> 5;
    const int nc = g_ncand[r];
    __shared__ float xs[8][DIM];
    int bk;

    if (nc <= MAXC) {
        const float thr = g_rowmin[r] + RMARGIN;
        float bestv = 3.4e38f;
        int bkk = KCB;
        const float4* xr = ((const float4*)x) + (size_t)r * 128;
        float4 xv[4];
#pragma unroll
        for (int q = 0; q < 4; q++) xv[q] = xr[lane + q * 32];
        for (int ci = 0; ci < nc; ci++) {
            if (g_cscore[r * MAXC + ci] > thr) continue;
            int k = g_cand[r * MAXC + ci];
            const float4* cr = ((const float4*)cb) + (size_t)k * 128;
            float pd = 0.f;
#pragma unroll
            for (int q = 0; q < 4; q++) {
                float4 c = cr[lane + q * 32];
                pd = fmaf(xv[q].x, c.x, pd); pd = fmaf(xv[q].y, c.y, pd);
                pd = fmaf(xv[q].z, c.z, pd); pd = fmaf(xv[q].w, c.w, pd);
            }
#pragma unroll
            for (int o = 16; o; o >>= 1) pd += __shfl_down_sync(0xffffffffu, pd, o);
            if (lane == 0) {
                float d2 = fmaf(-2.0f, pd, g_c2[k]);
                if (d2 < bestv || (d2 == bestv && k < bkk)) { bestv = d2; bkk = k; }
            }
        }
        bk = __shfl_sync(0xffffffffu, bkk, 0);
    } else {
        for (int d = lane; d < DIM; d += 32) xs[w][d] = x[(size_t)r * DIM + d];
        __syncwarp();
        const float thrfb = g_rowmin[r] + RMARGIN;
        int kl[8]; int cnt = 0;
        for (int k0 = lane; k0 < KCB; k0 += 32) {
            const uint2* crow = (const uint2*)(g_ch + (size_t)k0 * DIM);
            float dot = 0.f;
#pragma unroll 4
            for (int q = 0; q < 128; q++) {
                uint2 u = crow[q];
                float2 f0 = __half22float2(*(__half2*)&u.x);
                float2 f1 = __half22float2(*(__half2*)&u.y);
                dot += xs[w][4 * q] * f0.x + xs[w][4 * q + 1] * f0.y
                     + xs[w][4 * q + 2] * f1.x + xs[w][4 * q + 3] * f1.y;
            }
            float s = fmaf(-2.f, dot, g_c2[k0]);
            if (s <= thrfb && cnt < 8) kl[cnt++] = k0;
        }
        float bv = 3.4e38f; int bkk = KCB;
        for (int c = 0; c < cnt; c++) {
            int k = kl[c];
            const float* cr = cb + (size_t)k * DIM;
            float pd = 0.f;
            for (int d = 0; d < DIM; d++) pd = fmaf(xs[w][d], cr[d], pd);
            float d2 = fmaf(-2.0f, pd, g_c2[k]);
            if (d2 < bv || (d2 == bv && k < bkk)) { bv = d2; bkk = k; }
        }
        for (int o = 16; o; o >>= 1) {
            float ov = __shfl_down_sync(0xffffffffu, bv, o);
            int ok = __shfl_down_sync(0xffffffffu, bkk, o);
            if (ov < bv || (ov == bv && ok < bkk)) { bv = ov; bkk = ok; }
        }
        bk = __shfl_sync(0xffffffffu, bkk, 0);
    }

    const int s = r & (SEQ - 1);
    const float4* cr = ((const float4*)cb) + (size_t)bk * 128;
    const float4* pr = ((const float4*)g_pe) + (size_t)s * 128;
    float4* o4 = ((float4*)out) + (size_t)r * 128;
#pragma unroll
    for (int q = 0; q < 4; q++) {
        float4 c = cr[lane + q * 32], p = pr[lane + q * 32];
        o4[lane + q * 32] = make_float4(c.x + p.x, c.y + p.y, c.z + p.z, c.w + p.w);
    }
}

// ---------------- prep kernels ----------------
__global__ void k_prep_x(const float4* __restrict__ x) {
    int i = blockIdx.x * blockDim.x + threadIdx.x;
    if (i < NROWS * DIM / 4) {
        float4 v = x[i];
        __half2 a = __floats2half2_rn(v.x, v.y);
        __half2 b = __floats2half2_rn(v.z, v.w);
        reinterpret_cast<uint2*>(g_xh)[i] =
            make_uint2(*reinterpret_cast<uint32_t*>(&a), *reinterpret_cast<uint32_t*>(&b));
    }
    if (i < NROWS) g_ncand[i] = 0;
}

__global__ void k_prep_cb(const float* __restrict__ cb) {
    int row = blockIdx.x, tid = threadIdx.x;
    float p = 0.0f;
    for (int d = tid; d < DIM; d += 128) {
        float v = cb[(size_t)row * DIM + d];
        g_ch[(size_t)row * DIM + d] = __float2half_rn(v);
        p = fmaf(v, v, p);
    }
#pragma unroll
    for (int off = 16; off; off >>= 1) p += __shfl_down_sync(0xffffffffu, p, off);
    __shared__ float r4[4];
    if ((tid & 31) == 0) r4[tid >> 5] = p;
    __syncthreads();
    if (tid == 0) g_c2[row] = r4[0] + r4[1] + r4[2] + r4[3];
}

__global__ void k_prep_pe() {
    int s = blockIdx.x;
    int i = threadIdx.x;
    const float c = (float)(9.210340371976184 / 512.0);
    float dvf = expf(-(float)(2 * i) * c);
    float angf = (float)s * dvf;
    float n = rintf(angf * 0.15915494309189535f);
    float rf = (float)((double)angf - (double)n * 6.283185307179586477);
    g_pe[(size_t)s * DIM + 2 * i]     = sinf(rf);
    g_pe[(size_t)s * DIM + 2 * i + 1] = cosf(rf);
}

// ---------------- launch ----------------
extern "C" void kernel_launch(void* const* d_in, const int* in_sizes, int n_in,
                              void* d_out, int out_size) {
    const float* x  = (const float*)d_in[0];
    const float* cb = (const float*)d_in[1];
    float* out = (float*)d_out;

    cudaFuncSetAttribute(k_screen, cudaFuncAttributeMaxDynamicSharedMemorySize, SMEM_DYN);

    k_prep_x<<<(NROWS * DIM / 4 + 255) / 256, 256>>>((const float4*)x);
    k_prep_cb<<<KCB, 128>>>(cb);
    k_prep_pe<<<SEQ, 256>>>();
    k_screen<<<128, 512, SMEM_DYN>>>();
    k_select<<<NROWS / 8, 256>>>(x, cb, out);
}